// round 14
// baseline (speedup 1.0000x reference)
#include <cuda_runtime.h>
#include <math.h>

#define STEPF   0.1f
#define MAXL    2048
#define MAXNS   64
#define MAXNP   128
#define DELAY_N 30
#define TPB     128

typedef unsigned long long u64;

__device__ __forceinline__ u64 fma2(u64 a, u64 b, u64 c) {
    u64 d; asm("fma.rn.f32x2 %0, %1, %2, %3;" : "=l"(d) : "l"(a), "l"(b), "l"(c)); return d;
}
__device__ __forceinline__ u64 mul2(u64 a, u64 b) {
    u64 d; asm("mul.rn.f32x2 %0, %1, %2;" : "=l"(d) : "l"(a), "l"(b)); return d;
}
__device__ __forceinline__ u64 pack2(float lo, float hi) {
    u64 d; asm("mov.b64 %0, {%1, %2};" : "=l"(d) : "f"(lo), "f"(hi)); return d;
}
__device__ __forceinline__ u64 dup2(float v) { return pack2(v, v); }
__device__ __forceinline__ void unpack2(u64 v, float& lo, float& hi) {
    asm("mov.b64 {%0, %1}, %2;" : "=f"(lo), "=f"(hi) : "l"(v));
}
__device__ __forceinline__ float rcpf(float x) {
    float r; asm("rcp.approx.f32 %0, %1;" : "=f"(r) : "f"(x)); return r;
}

// full binary-search interp (reference-equivalent), fallback
__device__ __noinline__ float interp_full(float t, const float* st, const float* cp, int ns) {
    if (t <= st[0]) return cp[0];
    if (t >= st[ns - 1]) return cp[ns - 1];
    int lo = 0, hi = ns - 1;
    while (lo + 1 < hi) { int mid = (lo + hi) >> 1; if (st[mid] <= t) lo = mid; else hi = mid; }
    return cp[lo] + (t - st[lo]) * (cp[lo + 1] - cp[lo]) / (st[lo + 1] - st[lo]);
}

// guessed-bracket interp: identical result, ~10x fewer dependent LDS
__device__ __forceinline__ float interp_guess(float t, int guess,
                                              const float* st, const float* cp, int ns) {
    if (t <= st[0]) return cp[0];
    if (t >= st[ns - 1]) return cp[ns - 1];
    int lo = guess < 0 ? 0 : (guess > ns - 2 ? ns - 2 : guess);
    if (!(st[lo] <= t && t < st[lo + 1])) {
        if (lo > 0 && st[lo - 1] <= t && t < st[lo]) --lo;
        else if (lo < ns - 2 && st[lo + 1] <= t && t < st[lo + 2]) ++lo;
        else return interp_full(t, st, cp, ns);
    }
    return cp[lo] + (t - st[lo]) * (cp[lo + 1] - cp[lo]) / (st[lo + 1] - st[lo]);
}

struct PixCtx {
    u64 R, Rm1, ZAB;
    float d0, d1, d2, d3;     // Horner coeffs of u = 1 - c*E1*exp_taylor(z)
    float K1, K2;             // sig = K1 + K2 * rcp(u)
};

#define SIG_OF(ctx, Sv, dst) do {                                              \
    float _zl, _zh; unpack2(mul2((Sv), (ctx).ZAB), _zl, _zh);                  \
    const float _z = _zl + _zh;                                                \
    const float _u = fmaf(fmaf(fmaf(_z, (ctx).d3, (ctx).d2), _z, (ctx).d1), _z, (ctx).d0); \
    (dst) = fmaf((ctx).K2, rcpf(_u), (ctx).K1);                                \
} while (0)

// NPIECE = ns - 3 twelve-step pieces; emit j = k+3 at mid-piece (off-chain),
// knot-to-knot state jump = ONE dependent fma2 per output.
template <int NPIECE>
__device__ __forceinline__ void run_aligned(const PixCtx& ctx,
                                            const ulonglong2* __restrict__ s_pc,
                                            const ulonglong2* __restrict__ s_exq,
                                            float* optr, size_t stp)
{
    const u64 ONE = pack2(1.f, 1.f);
    const u64 R = ctx.R;
    const u64 R2 = mul2(R, R), R6 = mul2(mul2(R2, R2), R2);
    u64 G6 = fma2(R, ONE, ONE);
    G6 = fma2(G6, R, ONE); G6 = fma2(G6, R, ONE);
    G6 = fma2(G6, R, ONE); G6 = fma2(G6, R, ONE);            // 1+r+..+r^5
    u64 H6 = fma2(R, ONE, pack2(2.f, 2.f));
    H6 = fma2(H6, R, pack2(3.f, 3.f)); H6 = fma2(H6, R, pack2(4.f, 4.f));
    H6 = fma2(H6, R, pack2(5.f, 5.f)); H6 = fma2(H6, R, pack2(6.f, 6.f)); // Σ i·r^(6-i)

    const u64 R12 = mul2(R6, R6);
    const u64 G12 = fma2(G6, R6, G6);                        // G6·(1+r^6)
    const u64 H12 = fma2(G6, pack2(6.f, 6.f), fma2(H6, R6, H6)); // H6·(1+r^6)+6·G6

    float sig0; SIG_OF(ctx, 0ull, sig0);
    optr[0] = sig0; optr[stp] = sig0; optr[2 * stp] = sig0;
    optr += 3 * stp;

    u64 S = s_pc[0].x;                         // dup'd aif[30] (knot 0 state)

    #pragma unroll 8
    for (int k = 0; k < NPIECE; ++k) {
        const ulonglong2 p  = s_pc[k];         // {(A,A),(sl,sl)} — one LDS.128
        const ulonglong2 eq = s_exq[k + 3];    // {(flag,flag),(exf,exf)}
        const u64 Sm = fma2(S, R6, fma2(p.y, H6, mul2(p.x, G6)));   // mid (emit), off-chain
        const u64 W  = fma2(eq.x, ctx.Rm1, ONE);                    // 1 + flag*(r-1)
        const u64 Se = fma2(Sm, W, eq.y);                           // Sm*r^flag + flag*ex
        float sig; SIG_OF(ctx, Se, sig);
        *optr = sig; optr += stp;
        S = fma2(S, R12, fma2(p.y, H12, mul2(p.x, G12)));           // knot jump (chain)
    }
}

// ---------------------------------------------------------------------------
__global__ void __launch_bounds__(TPB, 6)
dce_kernel(const float* __restrict__ param,
           const float* __restrict__ sample_time,
           const float* __restrict__ Cp,
           float* __restrict__ out, int npix, int ns)
{
    __shared__ float s_st[MAXNS], s_cp[MAXNS];
    __shared__ __align__(16) ulonglong2 s_pc[MAXNS];   // per 12-step piece {(A,A),(sl,sl)}
    __shared__ __align__(16) ulonglong2 s_exq[MAXNS];  // per output {(flag,flag),(exf,exf)}
    __shared__ float s_av[MAXNP + 1];
    __shared__ int   s_idx[MAXNS];
    __shared__ int   s_ok;
    __shared__ float s_aif[MAXL];                      // fallback only

    const int tid = threadIdx.x;
    if (tid == 0) s_ok = 1;
    for (int j = tid; j < ns && j < MAXNS; j += TPB) { s_st[j] = sample_time[j]; s_cp[j] = Cp[j]; }
    __syncthreads();

    const int Ltrue = (int)llrint((double)s_st[ns - 1] / 0.1) + 1;
    const int L = Ltrue < MAXL ? Ltrue : MAXL;

    // searchsorted with verified guess (candidates 12j / 12j+1), binary fallback
    for (int j = tid; j < ns && j < MAXNS; j += TPB) {
        const float st = s_st[j];
        const int c = 12 * j;
        int lo = -1;
        if (c < L && !((float)c * STEPF < st)) {
            if (c == 0 || ((float)(c - 1) * STEPF < st)) lo = c;
        } else if (c < L) {
            if (c + 1 >= L) lo = L - 1;
            else if (!((float)(c + 1) * STEPF < st)) lo = c + 1;
        }
        if (lo < 0) {
            int a = 0, b = L;
            while (a < b) { int mid = (a + b) >> 1; if ((float)mid * STEPF < st) a = mid + 1; else b = mid; }
            lo = a < (L - 1) ? a : (L - 1);
        }
        s_idx[j] = lo;
        const int d = lo - 12 * j;
        if (d < 0 || d > 1) atomicAnd(&s_ok, 0);
    }
    __syncthreads();

    const int NPB = 2 * ns - 7;                        // boundary values count-1
    const int NPIECE = ns - 3;                         // 12-step pieces
    const int aligned = s_ok && ns >= 5 && ns <= MAXNS && NPB < MAXNP && Ltrue == 12 * (ns - 1) + 1;

    if (aligned) {
        for (int i = tid; i <= NPB; i += TPB)
            s_av[i] = interp_guess((float)(6 * i) * STEPF, i >> 1, s_st, s_cp, ns);
        __syncthreads();
        for (int k = tid; k < NPIECE; k += TPB) {
            const float A  = s_av[2 * k];
            const float sl = (s_av[2 * k + 1] - A) * (1.f / 6.f);  // per-step slope (segment linear)
            ulonglong2 q; q.x = dup2(A); q.y = dup2(sl);
            s_pc[k] = q;
        }
        for (int j = tid; j < ns && j < MAXNS; j += TPB) {
            const int d = s_idx[j] - 12 * j;           // 0 or 1
            const int m = 12 * j + 1;
            float exf = 0.f;
            if (d == 1 && m >= DELAY_N && m < L)
                exf = interp_guess((float)(m - DELAY_N) * STEPF, (m - DELAY_N) / 12, s_st, s_cp, ns);
            ulonglong2 q; q.x = dup2((float)d); q.y = dup2(exf);
            s_exq[j] = q;
        }
    } else {
        for (int i = tid; i < L; i += TPB)
            s_aif[i] = (i >= DELAY_N) ? interp_full((float)(i - DELAY_N) * STEPF, s_st, s_cp, ns) : 0.f;
    }
    __syncthreads();

    const int pix = blockIdx.x * TPB + tid;
    if (pix >= npix) return;

    // ---- per-pixel pharmacokinetic constants (fast-math; rcp.approx 2e-7 rel
    //      err invisible at 1e-3 tol) ----
    const float ve  = param[pix];
    const float vp  = param[npix + pix];
    const float fpp = param[2 * npix + pix];
    const float ps  = param[3 * npix + pix];

    const float rfpp = rcpf(fpp);
    const float Te = ve * rcpf(ps);
    const float T  = (vp + ve) * rfpp;
    const float Tc = vp * rfpp;
    const float s  = T + Te;
    const float disc = sqrtf(fmaxf(s * s - 4.f * Tc * Te, 0.f));
    const float inv2 = rcpf(2.f * Tc * Te);
    const float thp = (s + disc) * inv2;
    const float thm = (s - disc) * inv2;

    const float rm = expf(-thm * STEPF);
    const float rp = expf(-thp * STEPF);
    const float Lf = (float)L;
    const float SEm = (-expm1f(-thm * STEPF * Lf)) * rcpf(-expm1f(-thm * STEPF));
    const float SEp = (-expm1f(-thp * STEPF * Lf)) * rcpf(-expm1f(-thp * STEPF));

    const float cmv = 1.f - Te * thm;
    const float cpc = Te * thp - 1.f;
    const float inv_she = rcpf(SEm - SEp);
    const float inv_shp = rcpf(fmaf(cmv, SEm, cpc * SEp));
    const float alpha = vp * inv_shp * cmv + ve * inv_she;
    const float beta  = vp * inv_shp * cpc - ve * inv_she;
    const float Kz    = -(0.00487f * 4.3f);

    PixCtx ctx;
    ctx.R    = pack2(rm, rp);
    ctx.Rm1  = pack2(rm - 1.f, rp - 1.f);
    ctx.ZAB  = pack2(Kz * alpha, Kz * beta);
    {
        const float c  = 0.98480775301220806f;     // cos(10 deg)
        const float E1 = expf(-0.00487f);
        const float M0t = 100.f * __fdividef(1.f - c * E1, 1.f - E1);
        const float bse = 100.f - M0t * __fdividef(1.f - E1, 1.f - E1 * c);
        const float q = c * E1;
        ctx.d0 = 1.f - q; ctx.d1 = -q; ctx.d2 = -q * 0.5f; ctx.d3 = -q * (1.f / 6.f);
        const float rc = rcpf(c);
        ctx.K1 = bse + M0t * rc;
        ctx.K2 = M0t * (c - 1.f) * rc;
    }

    float* optr = out + pix;
    const size_t stp = (size_t)npix;

    if (aligned) {
        if (NPIECE == 47) {
            run_aligned<47>(ctx, s_pc, s_exq, optr, stp);
        } else {
            // generic aligned loop (runtime trip count)
            const u64 ONE = pack2(1.f, 1.f);
            const u64 R = ctx.R;
            const u64 R2 = mul2(R, R), R6 = mul2(mul2(R2, R2), R2);
            u64 G6 = fma2(R, ONE, ONE);
            G6 = fma2(G6, R, ONE); G6 = fma2(G6, R, ONE);
            G6 = fma2(G6, R, ONE); G6 = fma2(G6, R, ONE);
            u64 H6 = fma2(R, ONE, pack2(2.f, 2.f));
            H6 = fma2(H6, R, pack2(3.f, 3.f)); H6 = fma2(H6, R, pack2(4.f, 4.f));
            H6 = fma2(H6, R, pack2(5.f, 5.f)); H6 = fma2(H6, R, pack2(6.f, 6.f));
            const u64 R12 = mul2(R6, R6);
            const u64 G12 = fma2(G6, R6, G6);
            const u64 H12 = fma2(G6, pack2(6.f, 6.f), fma2(H6, R6, H6));

            float sig0; SIG_OF(ctx, 0ull, sig0);
            optr[0] = sig0; optr[stp] = sig0; optr[2 * stp] = sig0;
            optr += 3 * stp;

            u64 S = s_pc[0].x;
            for (int k = 0; k < NPIECE; ++k) {
                const ulonglong2 p  = s_pc[k];
                const ulonglong2 eq = s_exq[k + 3];
                const u64 Sm = fma2(S, R6, fma2(p.y, H6, mul2(p.x, G6)));
                const u64 W  = fma2(eq.x, ctx.Rm1, ONE);
                const u64 Se = fma2(Sm, W, eq.y);
                float sig; SIG_OF(ctx, Se, sig);
                *optr = sig; optr += stp;
                S = fma2(S, R12, fma2(p.y, H12, mul2(p.x, G12)));
            }
        }
    } else {
        // fallback: proven unit-step recurrence
        u64 S = 0ull;
        int m = 0;
        for (int j = 0; j < ns; ++j) {
            const int target = s_idx[j];
            #pragma unroll 4
            for (; m <= target; ++m) S = fma2(S, ctx.R, dup2(s_aif[m]));
            float sig; SIG_OF(ctx, S, sig);
            *optr = sig; optr += stp;
        }
    }
}

extern "C" void kernel_launch(void* const* d_in, const int* in_sizes, int n_in,
                              void* d_out, int out_size)
{
    const float* param       = (const float*)d_in[0];
    const float* sample_time = (const float*)d_in[1];
    const float* Cp          = (const float*)d_in[2];
    float* out = (float*)d_out;

    const int ns   = in_sizes[1];
    const int npix = in_sizes[0] / 4;

    dce_kernel<<<(npix + TPB - 1) / TPB, TPB>>>(param, sample_time, Cp, out, npix, ns);
}

// round 15
// speedup vs baseline: 1.0019x; 1.0019x over previous
#include <cuda_runtime.h>
#include <math.h>

#define STEPF   0.1f
#define MAXL    2048
#define MAXNS   64
#define MAXNP   128
#define DELAY_N 30
#define TPB     128

typedef unsigned long long u64;

__device__ __forceinline__ u64 fma2(u64 a, u64 b, u64 c) {
    u64 d; asm("fma.rn.f32x2 %0, %1, %2, %3;" : "=l"(d) : "l"(a), "l"(b), "l"(c)); return d;
}
__device__ __forceinline__ u64 mul2(u64 a, u64 b) {
    u64 d; asm("mul.rn.f32x2 %0, %1, %2;" : "=l"(d) : "l"(a), "l"(b)); return d;
}
__device__ __forceinline__ u64 pack2(float lo, float hi) {
    u64 d; asm("mov.b64 %0, {%1, %2};" : "=l"(d) : "f"(lo), "f"(hi)); return d;
}
__device__ __forceinline__ u64 dup2(float v) { return pack2(v, v); }
__device__ __forceinline__ void unpack2(u64 v, float& lo, float& hi) {
    asm("mov.b64 {%0, %1}, %2;" : "=f"(lo), "=f"(hi) : "l"(v));
}
__device__ __forceinline__ float rcpf(float x) {
    float r; asm("rcp.approx.f32 %0, %1;" : "=f"(r) : "f"(x)); return r;
}

// full binary-search interp (reference-equivalent), fallback
__device__ __noinline__ float interp_full(float t, const float* st, const float* cp, int ns) {
    if (t <= st[0]) return cp[0];
    if (t >= st[ns - 1]) return cp[ns - 1];
    int lo = 0, hi = ns - 1;
    while (lo + 1 < hi) { int mid = (lo + hi) >> 1; if (st[mid] <= t) lo = mid; else hi = mid; }
    return cp[lo] + (t - st[lo]) * (cp[lo + 1] - cp[lo]) / (st[lo + 1] - st[lo]);
}

// guessed-bracket interp: identical result, ~10x fewer dependent LDS
__device__ __forceinline__ float interp_guess(float t, int guess,
                                              const float* st, const float* cp, int ns) {
    if (t <= st[0]) return cp[0];
    if (t >= st[ns - 1]) return cp[ns - 1];
    int lo = guess < 0 ? 0 : (guess > ns - 2 ? ns - 2 : guess);
    if (!(st[lo] <= t && t < st[lo + 1])) {
        if (lo > 0 && st[lo - 1] <= t && t < st[lo]) --lo;
        else if (lo < ns - 2 && st[lo + 1] <= t && t < st[lo + 2]) ++lo;
        else return interp_full(t, st, cp, ns);
    }
    return cp[lo] + (t - st[lo]) * (cp[lo + 1] - cp[lo]) / (st[lo + 1] - st[lo]);
}

struct PixCtx {
    u64 R, Rm1, ZAB;
    float d0, d1, d2, d3;     // Horner coeffs of u = 1 - c*E1*exp_taylor(z)
    float K1, K2;             // sig = K1 + K2 * rcp(u)
};

#define SIG_OF(ctx, Sv, dst) do {                                              \
    float _zl, _zh; unpack2(mul2((Sv), (ctx).ZAB), _zl, _zh);                  \
    const float _z = _zl + _zh;                                                \
    const float _u = fmaf(fmaf(fmaf(_z, (ctx).d3, (ctx).d2), _z, (ctx).d1), _z, (ctx).d0); \
    (dst) = fmaf((ctx).K2, rcpf(_u), (ctx).K1);                                \
} while (0)

#define T6_OF(p)  fma2((p).y, H6,  mul2((p).x, G6))
#define T12_OF(p) fma2((p).y, H12, mul2((p).x, G12))

// Dual-chain aligned runner for odd NPIECE (= ns-3). Chain A: even knots
// (outputs 3,5,..), chain B: odd knots (outputs 4,6,..). Each chain advances
// 24 fine-steps per iteration -> 2x dependency-level parallelism.
template <int NPIECE>   // must be odd, >= 3
__device__ __forceinline__ void run_aligned(const PixCtx& ctx,
                                            const ulonglong2* __restrict__ s_pc,
                                            const ulonglong2* __restrict__ s_exq,
                                            float* optr, size_t stp)
{
    const u64 ONE = pack2(1.f, 1.f);
    const u64 R = ctx.R;
    const u64 R2 = mul2(R, R), R6 = mul2(mul2(R2, R2), R2);
    u64 G6 = fma2(R, ONE, ONE);
    G6 = fma2(G6, R, ONE); G6 = fma2(G6, R, ONE);
    G6 = fma2(G6, R, ONE); G6 = fma2(G6, R, ONE);                 // 1+r+..+r^5
    u64 H6 = fma2(R, ONE, pack2(2.f, 2.f));
    H6 = fma2(H6, R, pack2(3.f, 3.f)); H6 = fma2(H6, R, pack2(4.f, 4.f));
    H6 = fma2(H6, R, pack2(5.f, 5.f)); H6 = fma2(H6, R, pack2(6.f, 6.f)); // Σ i·r^(6-i)
    const u64 R12 = mul2(R6, R6);
    const u64 R24 = mul2(R12, R12);
    const u64 G12 = fma2(G6, R6, G6);                             // G6·(1+r^6)
    const u64 H12 = fma2(G6, pack2(6.f, 6.f), fma2(H6, R6, H6));  // H6·(1+r^6)+6·G6

    float sig0; SIG_OF(ctx, 0ull, sig0);
    optr[0] = sig0; optr[stp] = sig0; optr[2 * stp] = sig0;
    optr += 3 * stp;

    // preload piece 0; init both chains
    ulonglong2 pe = s_pc[0];
    u64 T6e  = T6_OF(pe);
    u64 T12e = T12_OF(pe);
    u64 SA = pe.x;                          // state at knot 0 (dup'd aif[30])
    u64 SB = fma2(SA, R12, T12e);           // state at knot 1

    const int NIT = (NPIECE - 1) / 2;       // 23 for NPIECE=47
    #pragma unroll 4
    for (int i = 0; i < NIT; ++i) {
        const ulonglong2 po  = s_pc[2 * i + 1];
        const ulonglong2 pe2 = s_pc[2 * i + 2];
        const ulonglong2 eqA = s_exq[3 + 2 * i];
        const ulonglong2 eqB = s_exq[4 + 2 * i];
        const u64 T6o  = T6_OF(po);
        const u64 T12o = T12_OF(po);
        const u64 T6e2  = T6_OF(pe2);
        const u64 T12e2 = T12_OF(pe2);

        // emit A: output j = 3+2i from chain A state (knot 2i), piece 2i
        const u64 SmA = fma2(SA, R6, T6e);
        const u64 WA  = fma2(eqA.x, ctx.Rm1, ONE);
        const u64 SeA = fma2(SmA, WA, eqA.y);
        float sigA; SIG_OF(ctx, SeA, sigA);
        optr[0] = sigA;

        // emit B: output j = 4+2i from chain B state (knot 2i+1), piece 2i+1
        const u64 SmB = fma2(SB, R6, T6o);
        const u64 WB  = fma2(eqB.x, ctx.Rm1, ONE);
        const u64 SeB = fma2(SmB, WB, eqB.y);
        float sigB; SIG_OF(ctx, SeB, sigB);
        optr[stp] = sigB;
        optr += 2 * stp;

        // advance both chains by 24 steps (independent)
        SA = fma2(SA, R24, fma2(T12e, R12, T12o));
        SB = fma2(SB, R24, fma2(T12o, R12, T12e2));

        T6e = T6e2; T12e = T12e2;
    }
    // tail: output j = 3+2*NIT (= ns-1) from chain A, piece NPIECE-1
    const ulonglong2 eqA = s_exq[3 + 2 * NIT];
    const u64 SmA = fma2(SA, R6, T6e);
    const u64 WA  = fma2(eqA.x, ctx.Rm1, ONE);
    const u64 SeA = fma2(SmA, WA, eqA.y);
    float sigl; SIG_OF(ctx, SeA, sigl);
    optr[0] = sigl;
}

// ---------------------------------------------------------------------------
__global__ void __launch_bounds__(TPB, 6)
dce_kernel(const float* __restrict__ param,
           const float* __restrict__ sample_time,
           const float* __restrict__ Cp,
           float* __restrict__ out, int npix, int ns)
{
    __shared__ float s_st[MAXNS], s_cp[MAXNS];
    __shared__ __align__(16) ulonglong2 s_pc[MAXNS];   // per 12-step piece {(A,A),(sl,sl)}
    __shared__ __align__(16) ulonglong2 s_exq[MAXNS];  // per output {(flag,flag),(exf,exf)}
    __shared__ float s_av[MAXNP + 1];
    __shared__ int   s_idx[MAXNS];
    __shared__ int   s_ok;
    __shared__ float s_aif[MAXL];                      // fallback only

    const int tid = threadIdx.x;
    if (tid == 0) s_ok = 1;
    for (int j = tid; j < ns && j < MAXNS; j += TPB) { s_st[j] = sample_time[j]; s_cp[j] = Cp[j]; }
    __syncthreads();

    const int Ltrue = (int)llrint((double)s_st[ns - 1] / 0.1) + 1;
    const int L = Ltrue < MAXL ? Ltrue : MAXL;

    // searchsorted with verified guess (candidates 12j / 12j+1), binary fallback
    for (int j = tid; j < ns && j < MAXNS; j += TPB) {
        const float st = s_st[j];
        const int c = 12 * j;
        int lo = -1;
        if (c < L && !((float)c * STEPF < st)) {
            if (c == 0 || ((float)(c - 1) * STEPF < st)) lo = c;
        } else if (c < L) {
            if (c + 1 >= L) lo = L - 1;
            else if (!((float)(c + 1) * STEPF < st)) lo = c + 1;
        }
        if (lo < 0) {
            int a = 0, b = L;
            while (a < b) { int mid = (a + b) >> 1; if ((float)mid * STEPF < st) a = mid + 1; else b = mid; }
            lo = a < (L - 1) ? a : (L - 1);
        }
        s_idx[j] = lo;
        const int d = lo - 12 * j;
        if (d < 0 || d > 1) atomicAnd(&s_ok, 0);
    }
    __syncthreads();

    const int NPB = 2 * ns - 7;
    const int NPIECE = ns - 3;
    const int aligned = s_ok && ns >= 5 && ns <= MAXNS && NPB < MAXNP && Ltrue == 12 * (ns - 1) + 1;

    if (aligned) {
        for (int i = tid; i <= NPB; i += TPB)
            s_av[i] = interp_guess((float)(6 * i) * STEPF, i >> 1, s_st, s_cp, ns);
        __syncthreads();
        for (int k = tid; k < NPIECE; k += TPB) {
            const float A  = s_av[2 * k];
            const float sl = (s_av[2 * k + 1] - A) * (1.f / 6.f);  // per-step slope (segment linear)
            ulonglong2 q; q.x = dup2(A); q.y = dup2(sl);
            s_pc[k] = q;
        }
        for (int j = tid; j < ns && j < MAXNS; j += TPB) {
            const int d = s_idx[j] - 12 * j;           // 0 or 1
            const int m = 12 * j + 1;
            float exf = 0.f;
            if (d == 1 && m >= DELAY_N && m < L)
                exf = interp_guess((float)(m - DELAY_N) * STEPF, (m - DELAY_N) / 12, s_st, s_cp, ns);
            ulonglong2 q; q.x = dup2((float)d); q.y = dup2(exf);
            s_exq[j] = q;
        }
    } else {
        for (int i = tid; i < L; i += TPB)
            s_aif[i] = (i >= DELAY_N) ? interp_full((float)(i - DELAY_N) * STEPF, s_st, s_cp, ns) : 0.f;
    }
    __syncthreads();

    const int pix = blockIdx.x * TPB + tid;
    if (pix >= npix) return;

    // ---- per-pixel pharmacokinetic constants (fast-math; rcp.approx 2e-7 rel
    //      err invisible at 1e-3 tol) ----
    const float ve  = param[pix];
    const float vp  = param[npix + pix];
    const float fpp = param[2 * npix + pix];
    const float ps  = param[3 * npix + pix];

    const float rfpp = rcpf(fpp);
    const float Te = ve * rcpf(ps);
    const float T  = (vp + ve) * rfpp;
    const float Tc = vp * rfpp;
    const float s  = T + Te;
    const float disc = sqrtf(fmaxf(s * s - 4.f * Tc * Te, 0.f));
    const float inv2 = rcpf(2.f * Tc * Te);
    const float thp = (s + disc) * inv2;
    const float thm = (s - disc) * inv2;

    const float rm = expf(-thm * STEPF);
    const float rp = expf(-thp * STEPF);
    const float Lf = (float)L;
    const float SEm = (-expm1f(-thm * STEPF * Lf)) * rcpf(-expm1f(-thm * STEPF));
    const float SEp = (-expm1f(-thp * STEPF * Lf)) * rcpf(-expm1f(-thp * STEPF));

    const float cmv = 1.f - Te * thm;
    const float cpc = Te * thp - 1.f;
    const float inv_she = rcpf(SEm - SEp);
    const float inv_shp = rcpf(fmaf(cmv, SEm, cpc * SEp));
    const float alpha = vp * inv_shp * cmv + ve * inv_she;
    const float beta  = vp * inv_shp * cpc - ve * inv_she;
    const float Kz    = -(0.00487f * 4.3f);

    PixCtx ctx;
    ctx.R    = pack2(rm, rp);
    ctx.Rm1  = pack2(rm - 1.f, rp - 1.f);
    ctx.ZAB  = pack2(Kz * alpha, Kz * beta);
    {
        const float c  = 0.98480775301220806f;     // cos(10 deg)
        const float E1 = expf(-0.00487f);
        const float M0t = 100.f * __fdividef(1.f - c * E1, 1.f - E1);
        const float bse = 100.f - M0t * __fdividef(1.f - E1, 1.f - E1 * c);
        const float q = c * E1;
        ctx.d0 = 1.f - q; ctx.d1 = -q; ctx.d2 = -q * 0.5f; ctx.d3 = -q * (1.f / 6.f);
        const float rc = rcpf(c);
        ctx.K1 = bse + M0t * rc;
        ctx.K2 = M0t * (c - 1.f) * rc;
    }

    float* optr = out + pix;
    const size_t stp = (size_t)npix;

    if (aligned) {
        if (NPIECE == 47) {
            run_aligned<47>(ctx, s_pc, s_exq, optr, stp);
        } else {
            // generic aligned loop (runtime trip count, single chain)
            const u64 ONE = pack2(1.f, 1.f);
            const u64 R = ctx.R;
            const u64 R2 = mul2(R, R), R6 = mul2(mul2(R2, R2), R2);
            u64 G6 = fma2(R, ONE, ONE);
            G6 = fma2(G6, R, ONE); G6 = fma2(G6, R, ONE);
            G6 = fma2(G6, R, ONE); G6 = fma2(G6, R, ONE);
            u64 H6 = fma2(R, ONE, pack2(2.f, 2.f));
            H6 = fma2(H6, R, pack2(3.f, 3.f)); H6 = fma2(H6, R, pack2(4.f, 4.f));
            H6 = fma2(H6, R, pack2(5.f, 5.f)); H6 = fma2(H6, R, pack2(6.f, 6.f));
            const u64 R12 = mul2(R6, R6);
            const u64 G12 = fma2(G6, R6, G6);
            const u64 H12 = fma2(G6, pack2(6.f, 6.f), fma2(H6, R6, H6));

            float sig0; SIG_OF(ctx, 0ull, sig0);
            optr[0] = sig0; optr[stp] = sig0; optr[2 * stp] = sig0;
            optr += 3 * stp;

            u64 S = s_pc[0].x;
            for (int k = 0; k < NPIECE; ++k) {
                const ulonglong2 p  = s_pc[k];
                const ulonglong2 eq = s_exq[k + 3];
                const u64 Sm = fma2(S, R6, T6_OF(p));
                const u64 W  = fma2(eq.x, ctx.Rm1, ONE);
                const u64 Se = fma2(Sm, W, eq.y);
                float sig; SIG_OF(ctx, Se, sig);
                *optr = sig; optr += stp;
                S = fma2(S, R12, T12_OF(p));
            }
        }
    } else {
        // fallback: proven unit-step recurrence
        u64 S = 0ull;
        int m = 0;
        for (int j = 0; j < ns; ++j) {
            const int target = s_idx[j];
            #pragma unroll 4
            for (; m <= target; ++m) S = fma2(S, ctx.R, dup2(s_aif[m]));
            float sig; SIG_OF(ctx, S, sig);
            *optr = sig; optr += stp;
        }
    }
}

extern "C" void kernel_launch(void* const* d_in, const int* in_sizes, int n_in,
                              void* d_out, int out_size)
{
    const float* param       = (const float*)d_in[0];
    const float* sample_time = (const float*)d_in[1];
    const float* Cp          = (const float*)d_in[2];
    float* out = (float*)d_out;

    const int ns   = in_sizes[1];
    const int npix = in_sizes[0] / 4;

    dce_kernel<<<(npix + TPB - 1) / TPB, TPB>>>(param, sample_time, Cp, out, npix, ns);
}

// round 16
// speedup vs baseline: 1.0171x; 1.0152x over previous
#include <cuda_runtime.h>
#include <math.h>

#define STEPF   0.1f
#define MAXL    2048
#define MAXNS   64
#define MAXNP   128
#define DELAY_N 30
#define TPB     128
#define PIXPB   64            // pixels per block (2 threads per pixel)

typedef unsigned long long u64;

__device__ __forceinline__ u64 fma2(u64 a, u64 b, u64 c) {
    u64 d; asm("fma.rn.f32x2 %0, %1, %2, %3;" : "=l"(d) : "l"(a), "l"(b), "l"(c)); return d;
}
__device__ __forceinline__ u64 mul2(u64 a, u64 b) {
    u64 d; asm("mul.rn.f32x2 %0, %1, %2;" : "=l"(d) : "l"(a), "l"(b)); return d;
}
__device__ __forceinline__ u64 pack2(float lo, float hi) {
    u64 d; asm("mov.b64 %0, {%1, %2};" : "=l"(d) : "f"(lo), "f"(hi)); return d;
}
__device__ __forceinline__ u64 dup2(float v) { return pack2(v, v); }
__device__ __forceinline__ void unpack2(u64 v, float& lo, float& hi) {
    asm("mov.b64 {%0, %1}, %2;" : "=f"(lo), "=f"(hi) : "l"(v));
}
__device__ __forceinline__ float rcpf(float x) {
    float r; asm("rcp.approx.f32 %0, %1;" : "=f"(r) : "f"(x)); return r;
}

// full binary-search interp (reference-equivalent), fallback
__device__ __noinline__ float interp_full(float t, const float* st, const float* cp, int ns) {
    if (t <= st[0]) return cp[0];
    if (t >= st[ns - 1]) return cp[ns - 1];
    int lo = 0, hi = ns - 1;
    while (lo + 1 < hi) { int mid = (lo + hi) >> 1; if (st[mid] <= t) lo = mid; else hi = mid; }
    return cp[lo] + (t - st[lo]) * (cp[lo + 1] - cp[lo]) / (st[lo + 1] - st[lo]);
}

// guessed-bracket interp: identical result, ~10x fewer dependent LDS
__device__ __forceinline__ float interp_guess(float t, int guess,
                                              const float* st, const float* cp, int ns) {
    if (t <= st[0]) return cp[0];
    if (t >= st[ns - 1]) return cp[ns - 1];
    int lo = guess < 0 ? 0 : (guess > ns - 2 ? ns - 2 : guess);
    if (!(st[lo] <= t && t < st[lo + 1])) {
        if (lo > 0 && st[lo - 1] <= t && t < st[lo]) --lo;
        else if (lo < ns - 2 && st[lo + 1] <= t && t < st[lo + 2]) ++lo;
        else return interp_full(t, st, cp, ns);
    }
    return cp[lo] + (t - st[lo]) * (cp[lo + 1] - cp[lo]) / (st[lo + 1] - st[lo]);
}

struct PixCtx {
    u64 R, Rm1, ZAB;
    float d0, d1, d2, d3;     // Horner coeffs of u = 1 - c*E1*exp_taylor(z)
    float K1, K2;             // sig = K1 + K2 * rcp(u)
};

#define SIG_OF(ctx, Sv, dst) do {                                              \
    float _zl, _zh; unpack2(mul2((Sv), (ctx).ZAB), _zl, _zh);                  \
    const float _z = _zl + _zh;                                                \
    const float _u = fmaf(fmaf(fmaf(_z, (ctx).d3, (ctx).d2), _z, (ctx).d1), _z, (ctx).d0); \
    (dst) = fmaf((ctx).K2, rcpf(_u), (ctx).K1);                                \
} while (0)

// Emits outputs j = k+3 for k in [KSTART, KEND). If KSTART==0 also emits the
// three constant outputs j=0..2; else fast-forwards the state through pieces
// [0, KSTART) without emitting (exact same recurrence, no comms needed).
// Each 12-step piece is two 6-step halves: addends share M = A*G6;
// half2 coefficient H6b = H6 + 6*G6 (piece is linear with A' = A + 6*sl).
template <int KSTART, int KEND>
__device__ __forceinline__ void run_span(const PixCtx& ctx,
                                         const ulonglong2* __restrict__ s_pc,
                                         const ulonglong2* __restrict__ s_exq,
                                         float* optr, size_t stp)
{
    const u64 ONE = pack2(1.f, 1.f);
    const u64 R = ctx.R;
    const u64 R2 = mul2(R, R), R6 = mul2(mul2(R2, R2), R2);
    u64 G6 = fma2(R, ONE, ONE);
    G6 = fma2(G6, R, ONE); G6 = fma2(G6, R, ONE);
    G6 = fma2(G6, R, ONE); G6 = fma2(G6, R, ONE);                 // 1+r+..+r^5
    u64 H6 = fma2(R, ONE, pack2(2.f, 2.f));
    H6 = fma2(H6, R, pack2(3.f, 3.f)); H6 = fma2(H6, R, pack2(4.f, 4.f));
    H6 = fma2(H6, R, pack2(5.f, 5.f)); H6 = fma2(H6, R, pack2(6.f, 6.f)); // Σ i·r^(6-i)
    const u64 H6b = fma2(G6, pack2(6.f, 6.f), H6);

    u64 S = s_pc[0].x;                         // state at knot 0 (dup'd aif[30])

    if (KSTART == 0) {
        float sig0; SIG_OF(ctx, 0ull, sig0);
        optr[0] = sig0; optr[stp] = sig0; optr[2 * stp] = sig0;
        optr += 3 * stp;
    } else {
        #pragma unroll 8
        for (int k = 0; k < KSTART; ++k) {     // no-emit fast-forward
            const ulonglong2 p = s_pc[k];
            const u64 M  = mul2(p.x, G6);
            const u64 Sm = fma2(S, R6, fma2(p.y, H6, M));
            S = fma2(Sm, R6, fma2(p.y, H6b, M));
        }
    }

    #pragma unroll 4
    for (int k = KSTART; k < KEND; ++k) {
        const ulonglong2 p  = s_pc[k];         // {(A,A),(sl,sl)} — one LDS.128
        const ulonglong2 eq = s_exq[k + 3];    // {(flag,flag),(exf,exf)}
        const u64 M  = mul2(p.x, G6);
        const u64 Sm = fma2(S, R6, fma2(p.y, H6, M));   // mid-piece state
        const u64 W  = fma2(eq.x, ctx.Rm1, ONE);        // 1 + flag*(r-1)
        const u64 Se = fma2(Sm, W, eq.y);               // Sm*r^flag + flag*ex
        float sig; SIG_OF(ctx, Se, sig);
        *optr = sig; optr += stp;
        S = fma2(Sm, R6, fma2(p.y, H6b, M));            // knot k+1
    }
}

// runtime-bounds version for generic ns
__device__ void run_span_rt(const PixCtx& ctx,
                            const ulonglong2* __restrict__ s_pc,
                            const ulonglong2* __restrict__ s_exq,
                            int kstart, int kend, float* optr, size_t stp)
{
    const u64 ONE = pack2(1.f, 1.f);
    const u64 R = ctx.R;
    const u64 R2 = mul2(R, R), R6 = mul2(mul2(R2, R2), R2);
    u64 G6 = fma2(R, ONE, ONE);
    G6 = fma2(G6, R, ONE); G6 = fma2(G6, R, ONE);
    G6 = fma2(G6, R, ONE); G6 = fma2(G6, R, ONE);
    u64 H6 = fma2(R, ONE, pack2(2.f, 2.f));
    H6 = fma2(H6, R, pack2(3.f, 3.f)); H6 = fma2(H6, R, pack2(4.f, 4.f));
    H6 = fma2(H6, R, pack2(5.f, 5.f)); H6 = fma2(H6, R, pack2(6.f, 6.f));
    const u64 H6b = fma2(G6, pack2(6.f, 6.f), H6);

    u64 S = s_pc[0].x;
    if (kstart == 0) {
        float sig0; SIG_OF(ctx, 0ull, sig0);
        optr[0] = sig0; optr[stp] = sig0; optr[2 * stp] = sig0;
        optr += 3 * stp;
    } else {
        for (int k = 0; k < kstart; ++k) {
            const ulonglong2 p = s_pc[k];
            const u64 M  = mul2(p.x, G6);
            const u64 Sm = fma2(S, R6, fma2(p.y, H6, M));
            S = fma2(Sm, R6, fma2(p.y, H6b, M));
        }
    }
    for (int k = kstart; k < kend; ++k) {
        const ulonglong2 p  = s_pc[k];
        const ulonglong2 eq = s_exq[k + 3];
        const u64 M  = mul2(p.x, G6);
        const u64 Sm = fma2(S, R6, fma2(p.y, H6, M));
        const u64 W  = fma2(eq.x, ctx.Rm1, ONE);
        const u64 Se = fma2(Sm, W, eq.y);
        float sig; SIG_OF(ctx, Se, sig);
        *optr = sig; optr += stp;
        S = fma2(Sm, R6, fma2(p.y, H6b, M));
    }
}

// ---------------------------------------------------------------------------
__global__ void __launch_bounds__(TPB, 10)
dce_kernel(const float* __restrict__ param,
           const float* __restrict__ sample_time,
           const float* __restrict__ Cp,
           float* __restrict__ out, int npix, int ns)
{
    __shared__ float s_st[MAXNS], s_cp[MAXNS];
    __shared__ __align__(16) ulonglong2 s_pc[MAXNS];   // per 12-step piece {(A,A),(sl,sl)}
    __shared__ __align__(16) ulonglong2 s_exq[MAXNS];  // per output {(flag,flag),(exf,exf)}
    __shared__ float s_av[MAXNP + 1];
    __shared__ int   s_idx[MAXNS];
    __shared__ int   s_ok;
    __shared__ float s_aif[MAXL];                      // fallback only

    const int tid = threadIdx.x;
    if (tid == 0) s_ok = 1;
    for (int j = tid; j < ns && j < MAXNS; j += TPB) { s_st[j] = sample_time[j]; s_cp[j] = Cp[j]; }
    __syncthreads();

    const int Ltrue = (int)llrint((double)s_st[ns - 1] / 0.1) + 1;
    const int L = Ltrue < MAXL ? Ltrue : MAXL;

    // searchsorted with verified guess (candidates 12j / 12j+1), binary fallback
    for (int j = tid; j < ns && j < MAXNS; j += TPB) {
        const float st = s_st[j];
        const int c = 12 * j;
        int lo = -1;
        if (c < L && !((float)c * STEPF < st)) {
            if (c == 0 || ((float)(c - 1) * STEPF < st)) lo = c;
        } else if (c < L) {
            if (c + 1 >= L) lo = L - 1;
            else if (!((float)(c + 1) * STEPF < st)) lo = c + 1;
        }
        if (lo < 0) {
            int a = 0, b = L;
            while (a < b) { int mid = (a + b) >> 1; if ((float)mid * STEPF < st) a = mid + 1; else b = mid; }
            lo = a < (L - 1) ? a : (L - 1);
        }
        s_idx[j] = lo;
        const int d = lo - 12 * j;
        if (d < 0 || d > 1) atomicAnd(&s_ok, 0);
    }
    __syncthreads();

    const int NPB = 2 * ns - 7;
    const int NPIECE = ns - 3;
    const int aligned = s_ok && ns >= 5 && ns <= MAXNS && NPB < MAXNP && Ltrue == 12 * (ns - 1) + 1;

    if (aligned) {
        for (int i = tid; i <= NPB; i += TPB)
            s_av[i] = interp_guess((float)(6 * i) * STEPF, i >> 1, s_st, s_cp, ns);
        __syncthreads();
        for (int k = tid; k < NPIECE; k += TPB) {
            const float A  = s_av[2 * k];
            const float sl = (s_av[2 * k + 1] - A) * (1.f / 6.f);  // per-step slope
            ulonglong2 q; q.x = dup2(A); q.y = dup2(sl);
            s_pc[k] = q;
        }
        for (int j = tid; j < ns && j < MAXNS; j += TPB) {
            const int d = s_idx[j] - 12 * j;           // 0 or 1
            const int m = 12 * j + 1;
            float exf = 0.f;
            if (d == 1 && m >= DELAY_N && m < L)
                exf = interp_guess((float)(m - DELAY_N) * STEPF, (m - DELAY_N) / 12, s_st, s_cp, ns);
            ulonglong2 q; q.x = dup2((float)d); q.y = dup2(exf);
            s_exq[j] = q;
        }
    } else {
        for (int i = tid; i < L; i += TPB)
            s_aif[i] = (i >= DELAY_N) ? interp_full((float)(i - DELAY_N) * STEPF, s_st, s_cp, ns) : 0.f;
    }
    __syncthreads();

    // 2 threads per pixel: sub=0 -> outputs [0, KA+3), sub=1 -> [KA+3, ns)
    const int pi  = tid & (PIXPB - 1);
    const int sub = tid >> 6;                  // warp-uniform (warps 0,1 vs 2,3)
    const int pix = blockIdx.x * PIXPB + pi;
    if (pix >= npix) return;

    // ---- per-pixel pharmacokinetic constants (duplicated across the pair) ----
    const float ve  = param[pix];
    const float vp  = param[npix + pix];
    const float fpp = param[2 * npix + pix];
    const float ps  = param[3 * npix + pix];

    const float rfpp = rcpf(fpp);
    const float Te = ve * rcpf(ps);
    const float T  = (vp + ve) * rfpp;
    const float Tc = vp * rfpp;
    const float s  = T + Te;
    const float disc = sqrtf(fmaxf(s * s - 4.f * Tc * Te, 0.f));
    const float inv2 = rcpf(2.f * Tc * Te);
    const float thp = (s + disc) * inv2;
    const float thm = (s - disc) * inv2;

    const float rm = expf(-thm * STEPF);
    const float rp = expf(-thp * STEPF);
    const float Lf = (float)L;
    // numerators: args scaled by L, away from the cancellation zone -> __expf ok
    const float SEm = (1.f - __expf(-thm * STEPF * Lf)) * rcpf(-expm1f(-thm * STEPF));
    const float SEp = (1.f - __expf(-thp * STEPF * Lf)) * rcpf(-expm1f(-thp * STEPF));

    const float cmv = 1.f - Te * thm;
    const float cpc = Te * thp - 1.f;
    const float inv_she = rcpf(SEm - SEp);
    const float inv_shp = rcpf(fmaf(cmv, SEm, cpc * SEp));
    const float alpha = vp * inv_shp * cmv + ve * inv_she;
    const float beta  = vp * inv_shp * cpc - ve * inv_she;
    const float Kz    = -(0.00487f * 4.3f);

    PixCtx ctx;
    ctx.R    = pack2(rm, rp);
    ctx.Rm1  = pack2(rm - 1.f, rp - 1.f);
    ctx.ZAB  = pack2(Kz * alpha, Kz * beta);
    {
        const float c  = 0.98480775301220806f;     // cos(10 deg)
        const float E1 = expf(-0.00487f);
        const float M0t = 100.f * __fdividef(1.f - c * E1, 1.f - E1);
        const float bse = 100.f - M0t * __fdividef(1.f - E1, 1.f - E1 * c);
        const float q = c * E1;
        ctx.d0 = 1.f - q; ctx.d1 = -q; ctx.d2 = -q * 0.5f; ctx.d3 = -q * (1.f / 6.f);
        const float rc = rcpf(c);
        ctx.K1 = bse + M0t * rc;
        ctx.K2 = M0t * (c - 1.f) * rc;
    }

    const size_t stp = (size_t)npix;

    if (aligned) {
        if (NPIECE == 47) {                    // ns == 50 fast path, KA = 24
            if (sub == 0) {
                run_span<0, 24>(ctx, s_pc, s_exq, out + pix, stp);
            } else {
                run_span<24, 47>(ctx, s_pc, s_exq, out + pix + 27 * stp, stp);
            }
        } else {
            const int KA = (NPIECE + 1) / 2;
            if (sub == 0) run_span_rt(ctx, s_pc, s_exq, 0, KA, out + pix, stp);
            else          run_span_rt(ctx, s_pc, s_exq, KA, NPIECE, out + pix + (KA + 3) * stp, stp);
        }
    } else {
        if (sub != 0) return;                  // fallback: one thread per pixel
        u64 S = 0ull;
        int m = 0;
        float* optr = out + pix;
        for (int j = 0; j < ns; ++j) {
            const int target = s_idx[j];
            #pragma unroll 4
            for (; m <= target; ++m) S = fma2(S, ctx.R, dup2(s_aif[m]));
            float sig; SIG_OF(ctx, S, sig);
            *optr = sig; optr += stp;
        }
    }
}

extern "C" void kernel_launch(void* const* d_in, const int* in_sizes, int n_in,
                              void* d_out, int out_size)
{
    const float* param       = (const float*)d_in[0];
    const float* sample_time = (const float*)d_in[1];
    const float* Cp          = (const float*)d_in[2];
    float* out = (float*)d_out;

    const int ns   = in_sizes[1];
    const int npix = in_sizes[0] / 4;

    const int blocks = (npix + PIXPB - 1) / PIXPB;
    dce_kernel<<<blocks, TPB>>>(param, sample_time, Cp, out, npix, ns);
}

// round 17
// speedup vs baseline: 1.1356x; 1.1165x over previous
#include <cuda_runtime.h>
#include <math.h>

#define STEPF   0.1f
#define MAXL    2048
#define MAXNS   64
#define MAXNP   128
#define DELAY_N 30
#define TPB     128

typedef unsigned long long u64;

__device__ __forceinline__ u64 fma2(u64 a, u64 b, u64 c) {
    u64 d; asm("fma.rn.f32x2 %0, %1, %2, %3;" : "=l"(d) : "l"(a), "l"(b), "l"(c)); return d;
}
__device__ __forceinline__ u64 mul2(u64 a, u64 b) {
    u64 d; asm("mul.rn.f32x2 %0, %1, %2;" : "=l"(d) : "l"(a), "l"(b)); return d;
}
__device__ __forceinline__ u64 pack2(float lo, float hi) {
    u64 d; asm("mov.b64 %0, {%1, %2};" : "=l"(d) : "f"(lo), "f"(hi)); return d;
}
__device__ __forceinline__ u64 dup2(float v) { return pack2(v, v); }
__device__ __forceinline__ void unpack2(u64 v, float& lo, float& hi) {
    asm("mov.b64 {%0, %1}, %2;" : "=f"(lo), "=f"(hi) : "l"(v));
}
__device__ __forceinline__ float rcpf(float x) {
    float r; asm("rcp.approx.f32 %0, %1;" : "=f"(r) : "f"(x)); return r;
}

// full binary-search interp (reference-equivalent), fallback
__device__ __noinline__ float interp_full(float t, const float* st, const float* cp, int ns) {
    if (t <= st[0]) return cp[0];
    if (t >= st[ns - 1]) return cp[ns - 1];
    int lo = 0, hi = ns - 1;
    while (lo + 1 < hi) { int mid = (lo + hi) >> 1; if (st[mid] <= t) lo = mid; else hi = mid; }
    return cp[lo] + (t - st[lo]) * (cp[lo + 1] - cp[lo]) / (st[lo + 1] - st[lo]);
}

// guessed-bracket interp: identical result, ~10x fewer dependent LDS
__device__ __forceinline__ float interp_guess(float t, int guess,
                                              const float* st, const float* cp, int ns) {
    if (t <= st[0]) return cp[0];
    if (t >= st[ns - 1]) return cp[ns - 1];
    int lo = guess < 0 ? 0 : (guess > ns - 2 ? ns - 2 : guess);
    if (!(st[lo] <= t && t < st[lo + 1])) {
        if (lo > 0 && st[lo - 1] <= t && t < st[lo]) --lo;
        else if (lo < ns - 2 && st[lo + 1] <= t && t < st[lo + 2]) ++lo;
        else return interp_full(t, st, cp, ns);
    }
    return cp[lo] + (t - st[lo]) * (cp[lo + 1] - cp[lo]) / (st[lo + 1] - st[lo]);
}

struct PixCtx {
    u64 R, ZAB;
    float d0, d1, d2, d3;     // Horner coeffs of u = 1 - c*E1*exp_taylor(z)
    float K1, K2;             // sig = K1 + K2 * rcp(u)
};

#define SIG_OF(ctx, Sv, dst) do {                                              \
    float _zl, _zh; unpack2(mul2((Sv), (ctx).ZAB), _zl, _zh);                  \
    const float _z = _zl + _zh;                                                \
    const float _u = fmaf(fmaf(fmaf(_z, (ctx).d3, (ctx).d2), _z, (ctx).d1), _z, (ctx).d0); \
    (dst) = fmaf((ctx).K2, rcpf(_u), (ctx).K1);                                \
} while (0)

// One thread per pixel; each 12-step piece in two 6-step halves sharing
// M = A*G6 (H6b = H6 + 6*G6). Emit via off-chain Sm, d_j handled by ALU select.
template <int NPIECE>
__device__ __forceinline__ void run_all(const PixCtx& ctx,
                                        const ulonglong2* __restrict__ s_pc,
                                        const ulonglong2* __restrict__ s_exq,
                                        float* optr, size_t stp)
{
    const u64 ONE = pack2(1.f, 1.f);
    const u64 R = ctx.R;
    const u64 R2 = mul2(R, R), R6 = mul2(mul2(R2, R2), R2);
    u64 G6 = fma2(R, ONE, ONE);
    G6 = fma2(G6, R, ONE); G6 = fma2(G6, R, ONE);
    G6 = fma2(G6, R, ONE); G6 = fma2(G6, R, ONE);                 // 1+r+..+r^5
    u64 H6 = fma2(R, ONE, pack2(2.f, 2.f));
    H6 = fma2(H6, R, pack2(3.f, 3.f)); H6 = fma2(H6, R, pack2(4.f, 4.f));
    H6 = fma2(H6, R, pack2(5.f, 5.f)); H6 = fma2(H6, R, pack2(6.f, 6.f)); // Σ i·r^(6-i)
    const u64 H6b = fma2(G6, pack2(6.f, 6.f), H6);

    float sig0; SIG_OF(ctx, 0ull, sig0);
    optr[0] = sig0; optr[stp] = sig0; optr[2 * stp] = sig0;
    optr += 3 * stp;

    u64 S = s_pc[0].x;                         // state at knot 0 (dup'd aif[30])

    #pragma unroll 8
    for (int k = 0; k < NPIECE; ++k) {
        const ulonglong2 p  = s_pc[k];         // {(A,A),(sl,sl)}
        const ulonglong2 eq = s_exq[k + 3];    // {flag01, (ex,ex)}
        const u64 M   = mul2(p.x, G6);
        const u64 Sm  = fma2(S, R6, fma2(p.y, H6, M));  // mid-piece (emit base)
        const u64 Sx  = fma2(Sm, R, eq.y);              // one extra step
        const u64 Se  = eq.x ? Sx : Sm;                 // ALU select on d_j
        float sig; SIG_OF(ctx, Se, sig);
        *optr = sig; optr += stp;
        S = fma2(Sm, R6, fma2(p.y, H6b, M));            // knot k+1
    }
}

__device__ void run_all_rt(const PixCtx& ctx,
                           const ulonglong2* __restrict__ s_pc,
                           const ulonglong2* __restrict__ s_exq,
                           int npiece, float* optr, size_t stp)
{
    const u64 ONE = pack2(1.f, 1.f);
    const u64 R = ctx.R;
    const u64 R2 = mul2(R, R), R6 = mul2(mul2(R2, R2), R2);
    u64 G6 = fma2(R, ONE, ONE);
    G6 = fma2(G6, R, ONE); G6 = fma2(G6, R, ONE);
    G6 = fma2(G6, R, ONE); G6 = fma2(G6, R, ONE);
    u64 H6 = fma2(R, ONE, pack2(2.f, 2.f));
    H6 = fma2(H6, R, pack2(3.f, 3.f)); H6 = fma2(H6, R, pack2(4.f, 4.f));
    H6 = fma2(H6, R, pack2(5.f, 5.f)); H6 = fma2(H6, R, pack2(6.f, 6.f));
    const u64 H6b = fma2(G6, pack2(6.f, 6.f), H6);

    float sig0; SIG_OF(ctx, 0ull, sig0);
    optr[0] = sig0; optr[stp] = sig0; optr[2 * stp] = sig0;
    optr += 3 * stp;

    u64 S = s_pc[0].x;
    for (int k = 0; k < npiece; ++k) {
        const ulonglong2 p  = s_pc[k];
        const ulonglong2 eq = s_exq[k + 3];
        const u64 M   = mul2(p.x, G6);
        const u64 Sm  = fma2(S, R6, fma2(p.y, H6, M));
        const u64 Sx  = fma2(Sm, R, eq.y);
        const u64 Se  = eq.x ? Sx : Sm;
        float sig; SIG_OF(ctx, Se, sig);
        *optr = sig; optr += stp;
        S = fma2(Sm, R6, fma2(p.y, H6b, M));
    }
}

// ---------------------------------------------------------------------------
__global__ void __launch_bounds__(TPB, 6)
dce_kernel(const float* __restrict__ param,
           const float* __restrict__ sample_time,
           const float* __restrict__ Cp,
           float* __restrict__ out, int npix, int ns)
{
    __shared__ float s_st[MAXNS], s_cp[MAXNS];
    __shared__ __align__(16) ulonglong2 s_pc[MAXNS];   // per 12-step piece {(A,A),(sl,sl)}
    __shared__ __align__(16) ulonglong2 s_exq[MAXNS];  // per output {flag01, (ex,ex)}
    __shared__ float s_av[MAXNP + 1];
    __shared__ int   s_idx[MAXNS];
    __shared__ int   s_ok;
    __shared__ float s_aif[MAXL];                      // fallback only

    const int tid = threadIdx.x;
    if (tid == 0) s_ok = 1;
    for (int j = tid; j < ns && j < MAXNS; j += TPB) { s_st[j] = sample_time[j]; s_cp[j] = Cp[j]; }
    __syncthreads();

    const int Ltrue = (int)llrint((double)s_st[ns - 1] / 0.1) + 1;
    const int L = Ltrue < MAXL ? Ltrue : MAXL;
    const int NPB = 2 * ns - 7;

    // Phase 2 (single barrier): searchsorted (guessed+verified) AND boundary interp
    for (int j = tid; j < ns && j < MAXNS; j += TPB) {
        const float st = s_st[j];
        const int c = 12 * j;
        int lo = -1;
        if (c < L && !((float)c * STEPF < st)) {
            if (c == 0 || ((float)(c - 1) * STEPF < st)) lo = c;
        } else if (c < L) {
            if (c + 1 >= L) lo = L - 1;
            else if (!((float)(c + 1) * STEPF < st)) lo = c + 1;
        }
        if (lo < 0) {
            int a = 0, b = L;
            while (a < b) { int mid = (a + b) >> 1; if ((float)mid * STEPF < st) a = mid + 1; else b = mid; }
            lo = a < (L - 1) ? a : (L - 1);
        }
        s_idx[j] = lo;
        const int d = lo - 12 * j;
        if (d < 0 || d > 1) atomicAnd(&s_ok, 0);
    }
    if (ns >= 5 && ns <= MAXNS && NPB < MAXNP) {
        for (int i = tid; i <= NPB; i += TPB)
            s_av[i] = interp_guess((float)(6 * i) * STEPF, i >> 1, s_st, s_cp, ns);
    }
    __syncthreads();

    const int NPIECE = ns - 3;
    const int aligned = s_ok && ns >= 5 && ns <= MAXNS && NPB < MAXNP && Ltrue == 12 * (ns - 1) + 1;

    if (aligned) {
        for (int k = tid; k < NPIECE; k += TPB) {
            const float A  = s_av[2 * k];
            const float sl = (s_av[2 * k + 1] - A) * (1.f / 6.f);
            ulonglong2 q; q.x = dup2(A); q.y = dup2(sl);
            s_pc[k] = q;
        }
        for (int j = tid; j < ns && j < MAXNS; j += TPB) {
            const int d = s_idx[j] - 12 * j;           // 0 or 1
            const int m = 12 * j + 1;
            float exf = 0.f;
            if (d == 1 && m >= DELAY_N && m < L)
                exf = interp_guess((float)(m - DELAY_N) * STEPF, (m - DELAY_N) / 12, s_st, s_cp, ns);
            ulonglong2 q; q.x = (u64)d; q.y = dup2(exf);
            s_exq[j] = q;
        }
    } else {
        for (int i = tid; i < L; i += TPB)
            s_aif[i] = (i >= DELAY_N) ? interp_full((float)(i - DELAY_N) * STEPF, s_st, s_cp, ns) : 0.f;
    }
    __syncthreads();

    const int pix = blockIdx.x * TPB + tid;
    if (pix >= npix) return;

    // ---- per-pixel pharmacokinetic constants (fast-math; rcp.approx 2e-7
    //      rel err invisible at 1e-3 tol) ----
    const float ve  = param[pix];
    const float vp  = param[npix + pix];
    const float fpp = param[2 * npix + pix];
    const float ps  = param[3 * npix + pix];

    const float rfpp = rcpf(fpp);
    const float Te = ve * rcpf(ps);
    const float T  = (vp + ve) * rfpp;
    const float Tc = vp * rfpp;
    const float s  = T + Te;
    const float disc = sqrtf(fmaxf(s * s - 4.f * Tc * Te, 0.f));
    const float inv2 = rcpf(2.f * Tc * Te);
    const float thp = (s + disc) * inv2;
    const float thm = (s - disc) * inv2;

    const float rm = expf(-thm * STEPF);
    const float rp = expf(-thp * STEPF);
    const float Lf = (float)L;
    const float SEm = (1.f - __expf(-thm * STEPF * Lf)) * rcpf(-expm1f(-thm * STEPF));
    const float SEp = (1.f - __expf(-thp * STEPF * Lf)) * rcpf(-expm1f(-thp * STEPF));

    const float cmv = 1.f - Te * thm;
    const float cpc = Te * thp - 1.f;
    const float inv_she = rcpf(SEm - SEp);
    const float inv_shp = rcpf(fmaf(cmv, SEm, cpc * SEp));
    const float alpha = vp * inv_shp * cmv + ve * inv_she;
    const float beta  = vp * inv_shp * cpc - ve * inv_she;
    const float Kz    = -(0.00487f * 4.3f);

    PixCtx ctx;
    ctx.R    = pack2(rm, rp);
    ctx.ZAB  = pack2(Kz * alpha, Kz * beta);
    {
        const float c  = 0.98480775301220806f;     // cos(10 deg)
        const float E1 = expf(-0.00487f);
        const float M0t = 100.f * __fdividef(1.f - c * E1, 1.f - E1);
        const float bse = 100.f - M0t * __fdividef(1.f - E1, 1.f - E1 * c);
        const float q = c * E1;
        ctx.d0 = 1.f - q; ctx.d1 = -q; ctx.d2 = -q * 0.5f; ctx.d3 = -q * (1.f / 6.f);
        const float rc = rcpf(c);
        ctx.K1 = bse + M0t * rc;
        ctx.K2 = M0t * (c - 1.f) * rc;
    }

    float* optr = out + pix;
    const size_t stp = (size_t)npix;

    if (aligned) {
        if (NPIECE == 47) run_all<47>(ctx, s_pc, s_exq, optr, stp);
        else              run_all_rt(ctx, s_pc, s_exq, NPIECE, optr, stp);
    } else {
        // fallback: proven unit-step recurrence
        u64 S = 0ull;
        int m = 0;
        for (int j = 0; j < ns; ++j) {
            const int target = s_idx[j];
            #pragma unroll 4
            for (; m <= target; ++m) S = fma2(S, ctx.R, dup2(s_aif[m]));
            float sig; SIG_OF(ctx, S, sig);
            *optr = sig; optr += stp;
        }
    }
}

extern "C" void kernel_launch(void* const* d_in, const int* in_sizes, int n_in,
                              void* d_out, int out_size)
{
    const float* param       = (const float*)d_in[0];
    const float* sample_time = (const float*)d_in[1];
    const float* Cp          = (const float*)d_in[2];
    float* out = (float*)d_out;

    const int ns   = in_sizes[1];
    const int npix = in_sizes[0] / 4;

    dce_kernel<<<(npix + TPB - 1) / TPB, TPB>>>(param, sample_time, Cp, out, npix, ns);
}